// round 14
// baseline (speedup 1.0000x reference)
#include <cuda_runtime.h>

// SGD_Hankel TT-chain: N=65536, L=128, D=4, R=8, O=2.
// R14: S=4 samples per lane, ONE warp per SMSP.
//   - 512 warp-units on 592 SMSPs: 128 CTAs x 128 thr, 1 CTA/SM, perfectly
//     balanced 512 samples/SM, no warp co-scheduling interference
//   - per step: R7's proven 2-sample body executed twice (pairs AB, CD with
//     independent merged state) -> high within-warp ILP covers LDS latency
//   - all 126 mid cores staged in smem ONCE (no phases, single __syncthreads)
//   - x staged in 2-step chunks: pv[8] register prefetch, swizzle
//     pos=(r+4s)&127 (conflict-free for STS.128 and LDS.128)

#define DV 4
#define RV 8
#define LV 128
#define NSTEP 126

typedef unsigned long long u64;

__device__ __forceinline__ u64 fpack(float a, float b) {
    u64 r; asm("mov.b64 %0, {%1,%2};" : "=l"(r) : "f"(a), "f"(b)); return r;
}
__device__ __forceinline__ u64 fdup(float a) {
    u64 r; asm("mov.b64 %0, {%1,%1};" : "=l"(r) : "f"(a)); return r;
}
__device__ __forceinline__ void funpack(u64 v, float& a, float& b) {
    asm("mov.b64 {%0,%1}, %2;" : "=f"(a), "=f"(b) : "l"(v));
}
__device__ __forceinline__ u64 f2mul(u64 a, u64 b) {
    u64 d; asm("mul.rn.f32x2 %0, %1, %2;" : "=l"(d) : "l"(a), "l"(b)); return d;
}
__device__ __forceinline__ u64 f2fma(u64 a, u64 b, u64 c) {
    u64 d; asm("fma.rn.f32x2 %0, %1, %2, %3;" : "=l"(d) : "l"(a), "l"(b), "l"(c)); return d;
}

// smem: ALL mid cores [126][3][8][8] + xbuf 4 warps * 1024 floats + first/last
#define SCORE_FLOATS (NSTEP * 3 * RV * RV)     // 24192
#define XBUF_FLOATS  (4 * 1024)                // 4096 (4KB per warp)
#define SFL_OFF      (SCORE_FLOATS + XBUF_FLOATS)
#define SMEM_FLOATS  (SFL_OFF + 96)
#define SMEM_BYTES   (SMEM_FLOATS * 4)         // 113536 (1 CTA/SM)

// 2-step x chunk c2 (steps 2*c2, 2*c2+1) for 128 samples: 8 LDG.128.
// lane -> (s = lane&1 step, g = lane>>1 group); rows r = g + 16*it.
__device__ __forceinline__ void ldg_chunk2(float4 (&pv)[8], const float* __restrict__ x,
                                           int base_w, int lane, int c2)
{
    const int s = lane & 1;
    const int g = lane >> 1;
    #pragma unroll
    for (int it = 0; it < 8; ++it) {
        int r = g + it * 16;                   // sample row 0..127
        pv[it] = *(const float4*)(x + (size_t)(base_w + r) * (LV * DV) + (c2 * 2 + s) * 4);
    }
}

// Publish chunk: 8 STS.128, layout [s][pos] float4 with pos=(r+4s)&127.
__device__ __forceinline__ void sts_chunk2(const float4 (&pv)[8], float* xw, int lane)
{
    const int s = lane & 1;
    const int g = lane >> 1;
    #pragma unroll
    for (int it = 0; it < 8; ++it) {
        int r = g + it * 16;
        int pos = (r + 4 * s) & 127;
        *(float4*)(xw + (s * 128 + pos) * 4) = pv[it];
    }
}

// One step of the chain for a 2-sample pair (R7's proven body).
__device__ __forceinline__ void step_pair(const float* __restrict__ cp,
                                          float4 xa, float4 xb,
                                          u64 (&mpA)[4], u64 (&mpB)[4])
{
    u64 mdA[8], mdB[8];
    #pragma unroll
    for (int p = 0; p < 4; ++p) {
        float a0, a1, b0, b1;
        funpack(mpA[p], a0, a1);
        funpack(mpB[p], b0, b1);
        mdA[2 * p] = fdup(a0); mdA[2 * p + 1] = fdup(a1);
        mdB[2 * p] = fdup(b0); mdB[2 * p + 1] = fdup(b1);
    }

    u64 Ya[3][4], Yb[3][4];
    #pragma unroll
    for (int j = 0; j < 3; ++j) {
        const float* cj = cp + j * 64;
        #pragma unroll
        for (int k = 0; k < 8; ++k) {
            ulonglong2 cA = *(const ulonglong2*)(cj + k * 8);
            ulonglong2 cB = *(const ulonglong2*)(cj + k * 8 + 4);
            if (k == 0) {
                Ya[j][0] = f2mul(mdA[0], cA.x); Ya[j][1] = f2mul(mdA[0], cA.y);
                Ya[j][2] = f2mul(mdA[0], cB.x); Ya[j][3] = f2mul(mdA[0], cB.y);
                Yb[j][0] = f2mul(mdB[0], cA.x); Yb[j][1] = f2mul(mdB[0], cA.y);
                Yb[j][2] = f2mul(mdB[0], cB.x); Yb[j][3] = f2mul(mdB[0], cB.y);
            } else {
                Ya[j][0] = f2fma(mdA[k], cA.x, Ya[j][0]);
                Ya[j][1] = f2fma(mdA[k], cA.y, Ya[j][1]);
                Ya[j][2] = f2fma(mdA[k], cB.x, Ya[j][2]);
                Ya[j][3] = f2fma(mdA[k], cB.y, Ya[j][3]);
                Yb[j][0] = f2fma(mdB[k], cA.x, Yb[j][0]);
                Yb[j][1] = f2fma(mdB[k], cA.y, Yb[j][1]);
                Yb[j][2] = f2fma(mdB[k], cB.x, Yb[j][2]);
                Yb[j][3] = f2fma(mdB[k], cB.y, Yb[j][3]);
            }
        }
    }

    // identity slice: j=3 term is x3 * merged (exact)
    const u64 a0 = fdup(xa.x), a1 = fdup(xa.y), a2 = fdup(xa.z), a3 = fdup(xa.w);
    const u64 b0 = fdup(xb.x), b1 = fdup(xb.y), b2 = fdup(xb.z), b3 = fdup(xb.w);
    #pragma unroll
    for (int p = 0; p < 4; ++p) {
        mpA[p] = f2fma(a3, mpA[p],
                 f2fma(a2, Ya[2][p],
                 f2fma(a1, Ya[1][p],
                 f2mul(a0, Ya[0][p]))));
        mpB[p] = f2fma(b3, mpB[p],
                 f2fma(b2, Yb[2][p],
                 f2fma(b1, Yb[1][p],
                 f2mul(b0, Yb[0][p]))));
    }
}

// Init merged for a pair from core_first.
__device__ __forceinline__ void init_pair(const float* __restrict__ sfirst,
                                          float4 xa, float4 xb,
                                          u64 (&mpA)[4], u64 (&mpB)[4])
{
    float mA[8], mB[8];
    #pragma unroll
    for (int k = 0; k < 8; ++k) {
        mA[k] = sfirst[k] * xa.x + sfirst[8 + k] * xa.y
              + sfirst[16 + k] * xa.z + sfirst[24 + k] * xa.w;
        mB[k] = sfirst[k] * xb.x + sfirst[8 + k] * xb.y
              + sfirst[16 + k] * xb.z + sfirst[24 + k] * xb.w;
    }
    #pragma unroll
    for (int p = 0; p < 4; ++p) {
        mpA[p] = fpack(mA[2 * p], mA[2 * p + 1]);
        mpB[p] = fpack(mB[2 * p], mB[2 * p + 1]);
    }
}

// Final contraction for a pair; writes out.
__device__ __forceinline__ void final_pair(const float* __restrict__ slast,
                                           float4 xa, float4 xb,
                                           const u64 (&mpA)[4], const u64 (&mpB)[4],
                                           float* __restrict__ out, int nA, int nB)
{
    u64 mdA[8], mdB[8];
    #pragma unroll
    for (int p = 0; p < 4; ++p) {
        float a0, a1, b0, b1;
        funpack(mpA[p], a0, a1);
        funpack(mpB[p], b0, b1);
        mdA[2 * p] = fdup(a0); mdA[2 * p + 1] = fdup(a1);
        mdB[2 * p] = fdup(b0); mdB[2 * p + 1] = fdup(b1);
    }
    u64 YlA[4], YlB[4];
    #pragma unroll
    for (int j = 0; j < 4; ++j) {
        u64 accA = f2mul(mdA[0], *(const u64*)(slast + j * 2));
        u64 accB = f2mul(mdB[0], *(const u64*)(slast + j * 2));
        #pragma unroll
        for (int k = 1; k < 8; ++k) {
            u64 cv = *(const u64*)(slast + (k * DV + j) * 2);
            accA = f2fma(mdA[k], cv, accA);
            accB = f2fma(mdB[k], cv, accB);
        }
        YlA[j] = accA; YlB[j] = accB;
    }
    u64 oA = f2fma(fdup(xa.w), YlA[3],
             f2fma(fdup(xa.z), YlA[2],
             f2fma(fdup(xa.y), YlA[1],
             f2mul(fdup(xa.x), YlA[0]))));
    u64 oB = f2fma(fdup(xb.w), YlB[3],
             f2fma(fdup(xb.z), YlB[2],
             f2fma(fdup(xb.y), YlB[1],
             f2mul(fdup(xb.x), YlB[0]))));
    float r0, r1;
    funpack(oA, r0, r1);
    { float2 res; res.x = r0; res.y = r1; *(float2*)(out + 2 * (size_t)nA) = res; }
    funpack(oB, r0, r1);
    { float2 res; res.x = r0; res.y = r1; *(float2*)(out + 2 * (size_t)nB) = res; }
}

extern "C" __global__ void __launch_bounds__(128, 1)
tt_chain_kernel(const float* __restrict__ x,
                const float* __restrict__ core_first,
                const float* __restrict__ cores_mid,
                const float* __restrict__ core_last,
                float* __restrict__ out,
                int n_total)
{
    extern __shared__ float sm[];
    float* score  = sm;                    // [126][3][8][8]
    float* xbuf   = sm + SCORE_FLOATS;
    float* sfirst = sm + SFL_OFF;          // 32 floats [j][k]
    float* slast  = sfirst + 32;           // 64 floats [k][j][l]

    const int tid  = threadIdx.x;
    const int lane = tid & 31;
    const int w    = tid >> 5;
    float* xw = xbuf + w * 1024;

    const int base_w = blockIdx.x * 512 + w * 128;   // warp covers 128 samples

    float4 pv[8];
    ldg_chunk2(pv, x, base_w, lane, 0);    // overlap with core staging

    // stage ALL mid cores: [s][k][j][l] -> [s][j][k][l], j<3
    for (int u = tid; u < NSTEP * 48; u += 128) {
        int st = u / 48;
        int rr = u - st * 48;
        int j = rr >> 4, k = (rr >> 1) & 7, h = rr & 1;
        float4 v = *(const float4*)(cores_mid
                    + (((size_t)st * RV + k) * DV + j) * RV + h * 4);
        *(float4*)(score + ((st * 3 + j) * RV + k) * RV + h * 4) = v;
    }
    if (tid < 32)       sfirst[tid] = core_first[tid];
    else if (tid < 96)  slast[tid - 32] = core_last[tid - 32];
    __syncthreads();

    // publish chunk 0 (steps 0,1), prefetch chunk 1
    sts_chunk2(pv, xw, lane);
    ldg_chunk2(pv, x, base_w, lane, 1);

    u64 mpA[4], mpB[4], mpC[4], mpD[4];
    {
        // l=0: s=0 -> pos = r
        float4 x0 = *(const float4*)(xw + ((lane)        & 127) * 4);
        float4 x1 = *(const float4*)(xw + ((lane + 32)   & 127) * 4);
        float4 x2 = *(const float4*)(xw + ((lane + 64)   & 127) * 4);
        float4 x3 = *(const float4*)(xw + ((lane + 96)   & 127) * 4);
        init_pair(sfirst, x0, x1, mpA, mpB);
        init_pair(sfirst, x2, x3, mpC, mpD);
    }

    const float* cp = score;
    #pragma unroll 1
    for (int l = 1; l <= NSTEP; ++l) {
        if ((l & 1) == 0) {
            // pv holds chunk c2=l/2 (LDG'd 2 steps ago)
            sts_chunk2(pv, xw, lane);              // warp-private: no sync
            const int c2 = l >> 1;
            if (c2 < 63) ldg_chunk2(pv, x, base_w, lane, c2 + 1);
        }
        const int s = l & 1;
        const int sb = s * 128;
        const int sh = 4 * s;

        float4 x0 = *(const float4*)(xw + (sb + ((lane      + sh) & 127)) * 4);
        float4 x1 = *(const float4*)(xw + (sb + ((lane + 32 + sh) & 127)) * 4);
        float4 x2 = *(const float4*)(xw + (sb + ((lane + 64 + sh) & 127)) * 4);
        float4 x3 = *(const float4*)(xw + (sb + ((lane + 96 + sh) & 127)) * 4);

        step_pair(cp, x0, x1, mpA, mpB);
        step_pair(cp, x2, x3, mpC, mpD);
        cp += 3 * 64;
    }

    // ---- final contraction (l=127, chunk 63 s=1) ----
    {
        const int sb = 128, sh = 4;
        float4 x0 = *(const float4*)(xw + (sb + ((lane      + sh) & 127)) * 4);
        float4 x1 = *(const float4*)(xw + (sb + ((lane + 32 + sh) & 127)) * 4);
        float4 x2 = *(const float4*)(xw + (sb + ((lane + 64 + sh) & 127)) * 4);
        float4 x3 = *(const float4*)(xw + (sb + ((lane + 96 + sh) & 127)) * 4);
        final_pair(slast, x0, x1, mpA, mpB, out, base_w + lane,      base_w + lane + 32);
        final_pair(slast, x2, x3, mpC, mpD, out, base_w + lane + 64, base_w + lane + 96);
    }
}

extern "C" void kernel_launch(void* const* d_in, const int* in_sizes, int n_in,
                              void* d_out, int out_size)
{
    const float* x  = (const float*)d_in[0];
    const float* cf = (const float*)d_in[1];
    const float* cm = (const float*)d_in[2];
    const float* cl = (const float*)d_in[3];
    float* out = (float*)d_out;

    const int n_total = in_sizes[0] / (LV * DV);   // 65536

    cudaFuncSetAttribute(tt_chain_kernel,
                         cudaFuncAttributeMaxDynamicSharedMemorySize, SMEM_BYTES);

    const int threads = 128;                       // 4 warps, 512 samples/CTA
    const int blocks = (n_total + 511) / 512;      // 128 CTAs -> 1 warp/SMSP
    tt_chain_kernel<<<blocks, threads, SMEM_BYTES>>>(x, cf, cm, cl, out, n_total);
}

// round 15
// speedup vs baseline: 1.7959x; 1.7959x over previous
#include <cuda_runtime.h>

// SGD_Hankel TT-chain: N=65536, L=128, D=4, R=8, O=2.  S=2 samples/thread.
// R15: R8 (== best 92.6us) with warp-staggered x-refill windows:
//   warp w refills at steps l = 2w + 8m instead of all warps at l = 8m.
//   De-synchronizes the 8 warps' LSU bursts in the per-SM L1tex queue.
//   Consumer side (slot = step & 7, swizzle pos=(r+slot)&63) is byte-
//   identical to R7/R8; only the refill schedule changes. Windows that
//   overhang step 127 clamp their loads into never-read slots.

#define DV 4
#define RV 8
#define LV 128
#define HALF  63

typedef unsigned long long u64;

__device__ __forceinline__ u64 fpack(float a, float b) {
    u64 r; asm("mov.b64 %0, {%1,%2};" : "=l"(r) : "f"(a), "f"(b)); return r;
}
__device__ __forceinline__ u64 fdup(float a) {
    u64 r; asm("mov.b64 %0, {%1,%1};" : "=l"(r) : "f"(a)); return r;
}
__device__ __forceinline__ void funpack(u64 v, float& a, float& b) {
    asm("mov.b64 {%0,%1}, %2;" : "=f"(a), "=f"(b) : "l"(v));
}
__device__ __forceinline__ u64 f2mul(u64 a, u64 b) {
    u64 d; asm("mul.rn.f32x2 %0, %1, %2;" : "=l"(d) : "l"(a), "l"(b)); return d;
}
__device__ __forceinline__ u64 f2fma(u64 a, u64 b, u64 c) {
    u64 d; asm("fma.rn.f32x2 %0, %1, %2, %3;" : "=l"(d) : "l"(a), "l"(b), "l"(c)); return d;
}

// smem: phased cores [63][3][8][8] + xbuf 4 warps * 2048 words + first/last
#define SCORE_FLOATS (HALF * 3 * RV * RV)      // 12096
#define XBUF_FLOATS  (4 * 2048)                // 8192
#define SFL_OFF      (SCORE_FLOATS + XBUF_FLOATS)
#define SMEM_FLOATS  (SFL_OFF + 96)
#define SMEM_BYTES   (SMEM_FLOATS * 4)         // 81536

// 16 coalesced LDG.128 for the 8-step window starting at step s0.
// Lanes with s0+s8 > 127 clamp to step 127 (data lands in unread slots).
__device__ __forceinline__ void ldg_win(float4 (&pv)[16], const float* __restrict__ x,
                                        int base_w, int lane, int s0)
{
    const int s8 = lane & 7;
    const int g  = lane >> 3;
    int step = s0 + s8;
    if (step > 127) step = 127;
    #pragma unroll
    for (int it = 0; it < 16; ++it) {
        int r = g + it * 4;                           // local row 0..63
        int n = base_w + ((r & 32) ? (r - 32 + 128) : r);
        pv[it] = *(const float4*)(x + (size_t)n * (LV * DV) + step * 4);
    }
}

// Publish the window: 16 STS.128 into slot = (s0+s8)&7, pos=(r+slot)&63.
// xbuf layout: [slot][pos] float4 (consumer at step l reads slot l&7).
__device__ __forceinline__ void sts_win(const float4 (&pv)[16], float* xw, int lane, int s0)
{
    const int s8 = lane & 7;
    const int g  = lane >> 3;
    const int slot = (s0 + s8) & 7;
    #pragma unroll
    for (int it = 0; it < 16; ++it) {
        int r = g + it * 4;
        int pos = (r + slot) & 63;
        *(float4*)(xw + (slot * 64 + pos) * 4) = pv[it];
    }
}

extern "C" __global__ void __launch_bounds__(128, 2)
tt_chain_kernel(const float* __restrict__ x,
                const float* __restrict__ core_first,
                const float* __restrict__ cores_mid,
                const float* __restrict__ core_last,
                float* __restrict__ out,
                int n_total)
{
    extern __shared__ float sm[];
    float* score  = sm;                    // [63][3][8][8]
    float* xbuf   = sm + SCORE_FLOATS;
    float* sfirst = sm + SFL_OFF;          // 32 floats [j][k]
    float* slast  = sfirst + 32;           // 64 floats [k][j][l]

    const int tid  = threadIdx.x;
    const int lane = tid & 31;
    const int w    = tid >> 5;
    const int off  = (w * 2) & 7;          // refill stagger: 0,2,4,6
    float* xw = xbuf + w * 2048;

    const int n0 = blockIdx.x * 256 + tid;
    const int n1 = n0 + 128;
    const int base_w = blockIdx.x * 256 + w * 32;

    float4 pv[16];
    // Prefetch window [0..7] immediately (overlaps core staging + barriers).
    ldg_win(pv, x, base_w, lane, 0);

    if (tid < 32)            sfirst[tid] = core_first[tid];
    else if (tid < 96)       slast[tid - 32] = core_last[tid - 32];

    u64 mpA[4], mpB[4];

    #pragma unroll 1
    for (int phase = 0; phase < 2; ++phase) {
        __syncthreads();    // prior-phase consumers done before core overwrite
        // stage cores for this phase: [s][k][j][l] -> [s][j][k][l], j<3
        for (int u = tid; u < HALF * 48; u += 128) {
            int st = u / 48;
            int rr = u - st * 48;
            int j = rr >> 4, k = (rr >> 1) & 7, h = rr & 1;
            float4 v = *(const float4*)(cores_mid
                        + (((size_t)(phase * HALF + st) * RV + k) * DV + j) * RV + h * 4);
            *(float4*)(score + ((st * 3 + j) * RV + k) * RV + h * 4) = v;
        }
        __syncthreads();

        if (phase == 0) {
            // publish window [0..7]; prefetch this warp's first staggered window
            sts_win(pv, xw, lane, 0);
            ldg_win(pv, x, base_w, lane, off == 0 ? 8 : off);

            // l=0: slot 0 -> pos = row
            float4 xa = *(const float4*)(xw + lane * 4);
            float4 xb = *(const float4*)(xw + (32 + lane) * 4);
            float mA[8], mB[8];
            #pragma unroll
            for (int k = 0; k < 8; ++k) {
                mA[k] = sfirst[k] * xa.x + sfirst[8 + k] * xa.y
                      + sfirst[16 + k] * xa.z + sfirst[24 + k] * xa.w;
                mB[k] = sfirst[k] * xb.x + sfirst[8 + k] * xb.y
                      + sfirst[16 + k] * xb.z + sfirst[24 + k] * xb.w;
            }
            #pragma unroll
            for (int p = 0; p < 4; ++p) {
                mpA[p] = fpack(mA[2 * p], mA[2 * p + 1]);
                mpB[p] = fpack(mB[2 * p], mB[2 * p + 1]);
            }
        }

        const float* cp = score;
        #pragma unroll 2
        for (int sc = 0; sc < HALF; ++sc) {
            const int l = phase * HALF + sc + 1;       // x index consumed this step
            if (((l - off) & 7) == 0) {
                // pv holds window [l..l+7] (LDG'd 8 steps ago -> arrived)
                sts_win(pv, xw, lane, l);              // warp-private: no sync
                if (l + 8 <= 126) ldg_win(pv, x, base_w, lane, l + 8);
            }
            const int s8 = l & 7;

            // x reads: one LDS.128 per sample (slot = l&7, same as R7)
            float4 xa = *(const float4*)(xw + (s8 * 64 + ((lane + s8) & 63)) * 4);
            float4 xb = *(const float4*)(xw + (s8 * 64 + ((lane + 32 + s8) & 63)) * 4);

            // duplicate merged scalars into packed lanes
            u64 mdA[8], mdB[8];
            #pragma unroll
            for (int p = 0; p < 4; ++p) {
                float a0, a1, b0, b1;
                funpack(mpA[p], a0, a1);
                funpack(mpB[p], b0, b1);
                mdA[2 * p] = fdup(a0); mdA[2 * p + 1] = fdup(a1);
                mdB[2 * p] = fdup(b0); mdB[2 * p + 1] = fdup(b1);
            }

            u64 Ya[3][4], Yb[3][4];
            #pragma unroll
            for (int j = 0; j < 3; ++j) {
                const float* cj = cp + j * 64;
                #pragma unroll
                for (int k = 0; k < 8; ++k) {
                    ulonglong2 cA = *(const ulonglong2*)(cj + k * 8);
                    ulonglong2 cB = *(const ulonglong2*)(cj + k * 8 + 4);
                    if (k == 0) {
                        Ya[j][0] = f2mul(mdA[0], cA.x); Ya[j][1] = f2mul(mdA[0], cA.y);
                        Ya[j][2] = f2mul(mdA[0], cB.x); Ya[j][3] = f2mul(mdA[0], cB.y);
                        Yb[j][0] = f2mul(mdB[0], cA.x); Yb[j][1] = f2mul(mdB[0], cA.y);
                        Yb[j][2] = f2mul(mdB[0], cB.x); Yb[j][3] = f2mul(mdB[0], cB.y);
                    } else {
                        Ya[j][0] = f2fma(mdA[k], cA.x, Ya[j][0]);
                        Ya[j][1] = f2fma(mdA[k], cA.y, Ya[j][1]);
                        Ya[j][2] = f2fma(mdA[k], cB.x, Ya[j][2]);
                        Ya[j][3] = f2fma(mdA[k], cB.y, Ya[j][3]);
                        Yb[j][0] = f2fma(mdB[k], cA.x, Yb[j][0]);
                        Yb[j][1] = f2fma(mdB[k], cA.y, Yb[j][1]);
                        Yb[j][2] = f2fma(mdB[k], cB.x, Yb[j][2]);
                        Yb[j][3] = f2fma(mdB[k], cB.y, Yb[j][3]);
                    }
                }
            }

            // identity slice: j=3 term is x3 * merged (exact)
            const u64 a0 = fdup(xa.x), a1 = fdup(xa.y), a2 = fdup(xa.z), a3 = fdup(xa.w);
            const u64 b0 = fdup(xb.x), b1 = fdup(xb.y), b2 = fdup(xb.z), b3 = fdup(xb.w);
            #pragma unroll
            for (int p = 0; p < 4; ++p) {
                mpA[p] = f2fma(a3, mpA[p],
                         f2fma(a2, Ya[2][p],
                         f2fma(a1, Ya[1][p],
                         f2mul(a0, Ya[0][p]))));
                mpB[p] = f2fma(b3, mpB[p],
                         f2fma(b2, Yb[2][p],
                         f2fma(b1, Yb[1][p],
                         f2mul(b0, Yb[0][p]))));
            }
            cp += 3 * 64;
        }
    }

    // ---- final contraction with core_last: out[l] = sum_j x_j (sum_k m_k C[k][j][l]) ----
    {
        const int s8 = 127 & 7;                // 7; step 127 published by last window
        float4 xa = *(const float4*)(xw + (s8 * 64 + ((lane + s8) & 63)) * 4);
        float4 xb = *(const float4*)(xw + (s8 * 64 + ((lane + 32 + s8) & 63)) * 4);

        u64 mdA[8], mdB[8];
        #pragma unroll
        for (int p = 0; p < 4; ++p) {
            float a0, a1, b0, b1;
            funpack(mpA[p], a0, a1);
            funpack(mpB[p], b0, b1);
            mdA[2 * p] = fdup(a0); mdA[2 * p + 1] = fdup(a1);
            mdB[2 * p] = fdup(b0); mdB[2 * p + 1] = fdup(b1);
        }
        u64 YlA[4], YlB[4];
        #pragma unroll
        for (int j = 0; j < 4; ++j) {
            u64 accA = f2mul(mdA[0], *(const u64*)(slast + j * 2));
            u64 accB = f2mul(mdB[0], *(const u64*)(slast + j * 2));
            #pragma unroll
            for (int k = 1; k < 8; ++k) {
                u64 cv = *(const u64*)(slast + (k * DV + j) * 2);
                accA = f2fma(mdA[k], cv, accA);
                accB = f2fma(mdB[k], cv, accB);
            }
            YlA[j] = accA; YlB[j] = accB;
        }
        u64 oA = f2fma(fdup(xa.w), YlA[3],
                 f2fma(fdup(xa.z), YlA[2],
                 f2fma(fdup(xa.y), YlA[1],
                 f2mul(fdup(xa.x), YlA[0]))));
        u64 oB = f2fma(fdup(xb.w), YlB[3],
                 f2fma(fdup(xb.z), YlB[2],
                 f2fma(fdup(xb.y), YlB[1],
                 f2mul(fdup(xb.x), YlB[0]))));
        float r0, r1;
        if (n0 < n_total) {
            funpack(oA, r0, r1);
            float2 res; res.x = r0; res.y = r1;
            *(float2*)(out + 2 * (size_t)n0) = res;
        }
        if (n1 < n_total) {
            funpack(oB, r0, r1);
            float2 res; res.x = r0; res.y = r1;
            *(float2*)(out + 2 * (size_t)n1) = res;
        }
    }
}

extern "C" void kernel_launch(void* const* d_in, const int* in_sizes, int n_in,
                              void* d_out, int out_size)
{
    const float* x  = (const float*)d_in[0];
    const float* cf = (const float*)d_in[1];
    const float* cm = (const float*)d_in[2];
    const float* cl = (const float*)d_in[3];
    float* out = (float*)d_out;

    const int n_total = in_sizes[0] / (LV * DV);   // 65536

    cudaFuncSetAttribute(tt_chain_kernel,
                         cudaFuncAttributeMaxDynamicSharedMemorySize, SMEM_BYTES);

    const int threads = 128;
    const int blocks = (n_total + 255) / 256;      // 2 samples per thread
    tt_chain_kernel<<<blocks, threads, SMEM_BYTES>>>(x, cf, cm, cl, out, n_total);
}